// round 1
// baseline (speedup 1.0000x reference)
#include <cuda_runtime.h>
#include <math.h>

#define BB 2
#define SS 2048
#define DIM 4096
#define NH 32
#define NKV 8
#define HD 128
#define MR (BB*SS)          // 4096 rows
#define KVDIM (NKV*HD)      // 1024

// ---- scratch (device globals; no allocation allowed) ----
__device__ float g_qf[(size_t)MR * DIM];     // Q proj, [row][h*128+d]
__device__ float g_kf[(size_t)MR * KVDIM];
__device__ float g_vf[(size_t)MR * KVDIM];
__device__ float g_q [(size_t)MR * DIM];     // [b][h][s][d]
__device__ float g_k [(size_t)MR * KVDIM];   // [b][kvh][s][d]
__device__ float g_v [(size_t)MR * KVDIM];
__device__ float g_at[(size_t)MR * DIM];     // attn out, [row][h*128+d]

// ============================================================
// NT GEMM: C[M,N] = A[M,K] * B[N,K]^T, all row-major fp32.
// BM=BN=64, BK=16, 256 threads, 4x4 per-thread tile.
// ============================================================
__global__ void gemm_nt(const float* __restrict__ A, const float* __restrict__ Bw,
                        float* __restrict__ C, int M, int N, int K) {
    __shared__ float As[16][64];
    __shared__ float Bs[16][64];
    const int t  = threadIdx.x;
    const int tx = t & 15, ty = t >> 4;
    const int bm = blockIdx.y * 64, bn = blockIdx.x * 64;

    const int lr = t >> 2;          // 0..63 (tile row)
    const int lk = (t & 3) << 2;    // 0,4,8,12 (tile k)
    const float* Ag = A  + (size_t)(bm + lr) * K + lk;
    const float* Bg = Bw + (size_t)(bn + lr) * K + lk;

    float4 a = *(const float4*)Ag;
    float4 b = *(const float4*)Bg;
    float acc[4][4] = {};

    for (int k0 = 0; k0 < K; k0 += 16) {
        As[lk+0][lr]=a.x; As[lk+1][lr]=a.y; As[lk+2][lr]=a.z; As[lk+3][lr]=a.w;
        Bs[lk+0][lr]=b.x; Bs[lk+1][lr]=b.y; Bs[lk+2][lr]=b.z; Bs[lk+3][lr]=b.w;
        __syncthreads();
        if (k0 + 16 < K) {
            a = *(const float4*)(Ag + k0 + 16);
            b = *(const float4*)(Bg + k0 + 16);
        }
        #pragma unroll
        for (int kk = 0; kk < 16; kk++) {
            float4 av = *(const float4*)&As[kk][ty << 2];
            float4 bv = *(const float4*)&Bs[kk][tx << 2];
            float ar[4] = {av.x, av.y, av.z, av.w};
            float br[4] = {bv.x, bv.y, bv.z, bv.w};
            #pragma unroll
            for (int i = 0; i < 4; i++)
                #pragma unroll
                for (int j = 0; j < 4; j++)
                    acc[i][j] += ar[i] * br[j];
        }
        __syncthreads();
    }
    #pragma unroll
    for (int i = 0; i < 4; i++) {
        float4 o = make_float4(acc[i][0], acc[i][1], acc[i][2], acc[i][3]);
        *(float4*)&C[(size_t)(bm + (ty << 2) + i) * N + bn + (tx << 2)] = o;
    }
}

// ============================================================
// RoPE + transpose to [b][h][s][d]
// ============================================================
__global__ void rope_q_kernel(const float* __restrict__ qf,
                              const float* __restrict__ fc,
                              const float* __restrict__ fs,
                              float* __restrict__ qo) {
    int idx = blockIdx.x * blockDim.x + threadIdx.x;   // MR*NH*64
    int p   = idx & 63;
    int h   = (idx >> 6) & (NH - 1);
    int row = idx >> 11;                   // b*SS+s
    int s   = row & (SS - 1);
    int b   = row >> 11;
    float2 tv = *(const float2*)&qf[(size_t)row * DIM + h * HD + 2 * p];
    float c = fc[s * 64 + p], sn = fs[s * 64 + p];
    float2 o = make_float2(tv.x * c - tv.y * sn, tv.x * sn + tv.y * c);
    *(float2*)&qo[(((size_t)(b * NH + h)) * SS + s) * HD + 2 * p] = o;
}

__global__ void rope_k_kernel(const float* __restrict__ kf,
                              const float* __restrict__ fc,
                              const float* __restrict__ fs,
                              float* __restrict__ ko) {
    int idx = blockIdx.x * blockDim.x + threadIdx.x;   // MR*NKV*64
    int p   = idx & 63;
    int h   = (idx >> 6) & (NKV - 1);
    int row = idx >> 9;
    int s   = row & (SS - 1);
    int b   = row >> 11;
    float2 tv = *(const float2*)&kf[(size_t)row * KVDIM + h * HD + 2 * p];
    float c = fc[s * 64 + p], sn = fs[s * 64 + p];
    float2 o = make_float2(tv.x * c - tv.y * sn, tv.x * sn + tv.y * c);
    *(float2*)&ko[(((size_t)(b * NKV + h)) * SS + s) * HD + 2 * p] = o;
}

__global__ void v_tr_kernel(const float* __restrict__ vf, float* __restrict__ vo) {
    int idx = blockIdx.x * blockDim.x + threadIdx.x;   // MR*KVDIM/4 float4s
    int d4  = idx & 31;
    int h   = (idx >> 5) & (NKV - 1);
    int row = idx >> 8;
    int s   = row & (SS - 1);
    int b   = row >> 11;
    float4 v = ((const float4*)vf)[idx];
    ((float4*)vo)[(((size_t)(b * NKV + h)) * SS + s) * (HD / 4) + d4] = v;
}

// ============================================================
// Flash attention fp32. 256 threads, Q tile 32 rows, K tile 32.
// thread t: row m = t>>3, octet oct = t&7.
//   score cols:  kk = oct + 8j (j=0..3)  -> conflict-free K float4 reads
//   output dims: d  = oct + 8jj (jj=0..15) -> conflict-free V scalar reads
// P held in registers, broadcast via 8-lane shuffles.
// ============================================================
__global__ void attn_kernel(const float* __restrict__ Q, const float* __restrict__ Kt,
                            const float* __restrict__ Vt, float* __restrict__ O) {
    __shared__ float Qs[32][132];
    __shared__ float KVs[32][132];
    const int qt = blockIdx.x, h = blockIdx.y, b = blockIdx.z;
    const int kvh = h >> 2;
    const int q0 = qt * 32;
    const float* qbase = Q  + (((size_t)(b * NH  + h  )) * SS + q0) * HD;
    const float* kbase = Kt + (((size_t)(b * NKV + kvh)) * SS) * HD;
    const float* vbase = Vt + (((size_t)(b * NKV + kvh)) * SS) * HD;
    const int t = threadIdx.x;
    const int m = t >> 3, oct = t & 7;

    for (int i = t; i < 1024; i += 256) {
        int r = i >> 5, c = i & 31;
        *(float4*)&Qs[r][c << 2] = ((const float4*)qbase)[i];
    }

    float mx = -INFINITY, l = 0.f;
    float acc[16];
    #pragma unroll
    for (int j = 0; j < 16; j++) acc[j] = 0.f;
    const float scale = 0.08838834764831845f;  // 1/sqrt(128)

    for (int k0 = 0; k0 <= q0; k0 += 32) {
        __syncthreads();   // KVs free (prev PV done); also fences Q on 1st iter
        for (int i = t; i < 1024; i += 256) {
            int r = i >> 5, c = i & 31;
            *(float4*)&KVs[r][c << 2] = ((const float4*)(kbase + (size_t)k0 * HD))[i];
        }
        __syncthreads();

        float s0 = 0, s1 = 0, s2 = 0, s3 = 0;
        #pragma unroll 8
        for (int d4 = 0; d4 < 32; d4++) {
            float4 qv  = *(const float4*)&Qs[m][d4 << 2];
            float4 k0v = *(const float4*)&KVs[oct     ][d4 << 2];
            float4 k1v = *(const float4*)&KVs[oct +  8][d4 << 2];
            float4 k2v = *(const float4*)&KVs[oct + 16][d4 << 2];
            float4 k3v = *(const float4*)&KVs[oct + 24][d4 << 2];
            s0 += qv.x*k0v.x + qv.y*k0v.y + qv.z*k0v.z + qv.w*k0v.w;
            s1 += qv.x*k1v.x + qv.y*k1v.y + qv.z*k1v.z + qv.w*k1v.w;
            s2 += qv.x*k2v.x + qv.y*k2v.y + qv.z*k2v.z + qv.w*k2v.w;
            s3 += qv.x*k3v.x + qv.y*k3v.y + qv.z*k3v.z + qv.w*k3v.w;
        }
        s0 *= scale; s1 *= scale; s2 *= scale; s3 *= scale;
        if (k0 == q0) {
            int qg = q0 + m;
            if (k0 + oct      > qg) s0 = -1e30f;
            if (k0 + oct +  8 > qg) s1 = -1e30f;
            if (k0 + oct + 16 > qg) s2 = -1e30f;
            if (k0 + oct + 24 > qg) s3 = -1e30f;
        }
        float tm = fmaxf(fmaxf(s0, s1), fmaxf(s2, s3));
        #pragma unroll
        for (int o = 1; o < 8; o <<= 1)
            tm = fmaxf(tm, __shfl_xor_sync(0xffffffffu, tm, o));
        float mn = fmaxf(mx, tm);
        float p0 = __expf(s0 - mn), p1 = __expf(s1 - mn);
        float p2 = __expf(s2 - mn), p3 = __expf(s3 - mn);
        float ls = p0 + p1 + p2 + p3;
        #pragma unroll
        for (int o = 1; o < 8; o <<= 1)
            ls += __shfl_xor_sync(0xffffffffu, ls, o);
        float csc = __expf(mx - mn);
        l = l * csc + ls;
        mx = mn;
        #pragma unroll
        for (int j = 0; j < 16; j++) acc[j] *= csc;

        __syncthreads();   // done reading K
        for (int i = t; i < 1024; i += 256) {
            int r = i >> 5, c = i & 31;
            *(float4*)&KVs[r][c << 2] = ((const float4*)(vbase + (size_t)k0 * HD))[i];
        }
        __syncthreads();

        float pr[4] = {p0, p1, p2, p3};
        #pragma unroll
        for (int kk = 0; kk < 32; kk++) {
            float p = __shfl_sync(0xffffffffu, pr[kk >> 3], kk & 7, 8);
            #pragma unroll
            for (int jj = 0; jj < 16; jj++)
                acc[jj] += p * KVs[kk][oct + (jj << 3)];
        }
    }

    float inv = 1.f / l;
    float* orow = O + ((size_t)(b * SS) + q0 + m) * DIM + h * HD;
    #pragma unroll
    for (int jj = 0; jj < 16; jj++)
        orow[oct + (jj << 3)] = acc[jj] * inv;
}

// ============================================================
extern "C" void kernel_launch(void* const* d_in, const int* in_sizes, int n_in,
                              void* d_out, int out_size) {
    const float* x  = (const float*)d_in[0];
    const float* wq = (const float*)d_in[1];
    const float* wk = (const float*)d_in[2];
    const float* wv = (const float*)d_in[3];
    const float* wo = (const float*)d_in[4];
    const float* fc = (const float*)d_in[5];
    const float* fs = (const float*)d_in[6];
    float* out = (float*)d_out;

    float *qf, *kf, *vf, *q, *k, *v, *at;
    cudaGetSymbolAddress((void**)&qf, g_qf);
    cudaGetSymbolAddress((void**)&kf, g_kf);
    cudaGetSymbolAddress((void**)&vf, g_vf);
    cudaGetSymbolAddress((void**)&q,  g_q);
    cudaGetSymbolAddress((void**)&k,  g_k);
    cudaGetSymbolAddress((void**)&v,  g_v);
    cudaGetSymbolAddress((void**)&at, g_at);

    // QKV projections
    gemm_nt<<<dim3(DIM   / 64, MR / 64), 256>>>(x, wq, qf, MR, DIM,   DIM);
    gemm_nt<<<dim3(KVDIM / 64, MR / 64), 256>>>(x, wk, kf, MR, KVDIM, DIM);
    gemm_nt<<<dim3(KVDIM / 64, MR / 64), 256>>>(x, wv, vf, MR, KVDIM, DIM);

    // RoPE + layout transforms
    rope_q_kernel<<<(MR * NH  * 64) / 256, 256>>>(qf, fc, fs, q);
    rope_k_kernel<<<(MR * NKV * 64) / 256, 256>>>(kf, fc, fs, k);
    v_tr_kernel  <<<(MR * KVDIM / 4) / 256, 256>>>(vf, v);

    // causal GQA attention
    attn_kernel<<<dim3(SS / 32, NH, BB), 256>>>(q, k, v, at);

    // output projection
    gemm_nt<<<dim3(DIM / 64, MR / 64), 256>>>(at, wo, out, MR, DIM, DIM);
}

// round 2
// speedup vs baseline: 1.8954x; 1.8954x over previous
#include <cuda_runtime.h>
#include <math.h>

#define BB 2
#define SS 2048
#define DIM 4096
#define NH 32
#define NKV 8
#define HD 128
#define MR (BB*SS)          // 4096 rows
#define KVDIM (NKV*HD)      // 1024

// ---- scratch (device globals; no allocation allowed) ----
__device__ float g_qf[(size_t)MR * DIM];     // Q proj, [row][h*128+d]
__device__ float g_kf[(size_t)MR * KVDIM];
__device__ float g_vf[(size_t)MR * KVDIM];
__device__ float g_q [(size_t)MR * DIM];     // [b][h][s][d]
__device__ float g_k [(size_t)MR * KVDIM];   // [b][kvh][s][d]
__device__ float g_v [(size_t)MR * KVDIM];
__device__ float g_at[(size_t)MR * DIM];     // attn out, [row][h*128+d]

// ============================================================
// tf32 tensor-core NT GEMM: C[M,N] = A[M,K] * B[N,K]^T (row-major fp32)
// BM=BN=128, BK=16, 256 threads (8 warps as 4Mx2N), warp tile 32x64.
// mma.sync.m16n8k8.tf32, cp.async double buffering.
// Smem row stride 20 floats => fragment LDS bank = 4*g + l4 = lane id
// (conflict-free).
// ============================================================
#define LDST 20

__device__ __forceinline__ unsigned f2tf(float v) {
    unsigned r;
    asm("cvt.rna.tf32.f32 %0, %1;" : "=r"(r) : "f"(v));
    return r;
}

__device__ __forceinline__ void mma1688(float* c, const unsigned* a, const unsigned* b) {
    asm volatile(
        "mma.sync.aligned.m16n8k8.row.col.f32.tf32.tf32.f32 "
        "{%0,%1,%2,%3}, {%4,%5,%6,%7}, {%8,%9}, {%0,%1,%2,%3};\n"
        : "+f"(c[0]), "+f"(c[1]), "+f"(c[2]), "+f"(c[3])
        : "r"(a[0]), "r"(a[1]), "r"(a[2]), "r"(a[3]), "r"(b[0]), "r"(b[1]));
}

__global__ __launch_bounds__(256, 2)
void gemm_nt_tf32(const float* __restrict__ A, const float* __restrict__ Bw,
                  float* __restrict__ C, int M, int N, int K) {
    __shared__ float As[2][128 * LDST];
    __shared__ float Bs[2][128 * LDST];
    const int t = threadIdx.x;
    const int bm = blockIdx.y * 128, bn = blockIdx.x * 128;

    // loader mapping: 2 threads per row, 8 consecutive floats each
    const int lrow = t >> 1, lc = (t & 1) * 8;
    const float* Ag = A  + (size_t)(bm + lrow) * K + lc;
    const float* Bg = Bw + (size_t)(bn + lrow) * K + lc;
    const unsigned sa0 = (unsigned)__cvta_generic_to_shared(&As[0][lrow * LDST + lc]);
    const unsigned sa1 = (unsigned)__cvta_generic_to_shared(&As[1][lrow * LDST + lc]);
    const unsigned sb0 = (unsigned)__cvta_generic_to_shared(&Bs[0][lrow * LDST + lc]);
    const unsigned sb1 = (unsigned)__cvta_generic_to_shared(&Bs[1][lrow * LDST + lc]);

    const int lane = t & 31, warp = t >> 5;
    const int wm = (warp >> 1) * 32, wn = (warp & 1) * 64;
    const int g = lane >> 2, l4 = lane & 3;

    float acc[2][8][4];
    #pragma unroll
    for (int mi = 0; mi < 2; mi++)
        #pragma unroll
        for (int ni = 0; ni < 8; ni++)
            #pragma unroll
            for (int j = 0; j < 4; j++) acc[mi][ni][j] = 0.f;

    const int niter = K / 16;

    // prefetch tile 0
    {
        asm volatile("cp.async.cg.shared.global [%0], [%1], 16;\n" :: "r"(sa0),      "l"(Ag));
        asm volatile("cp.async.cg.shared.global [%0], [%1], 16;\n" :: "r"(sa0 + 16), "l"(Ag + 4));
        asm volatile("cp.async.cg.shared.global [%0], [%1], 16;\n" :: "r"(sb0),      "l"(Bg));
        asm volatile("cp.async.cg.shared.global [%0], [%1], 16;\n" :: "r"(sb0 + 16), "l"(Bg + 4));
        asm volatile("cp.async.commit_group;\n");
    }

    for (int it = 0; it < niter; it++) {
        asm volatile("cp.async.wait_group 0;\n");
        __syncthreads();

        if (it + 1 < niter) {
            const int k0 = (it + 1) * 16;
            const unsigned da = (it & 1) ? sa0 : sa1;
            const unsigned db = (it & 1) ? sb0 : sb1;
            asm volatile("cp.async.cg.shared.global [%0], [%1], 16;\n" :: "r"(da),      "l"(Ag + k0));
            asm volatile("cp.async.cg.shared.global [%0], [%1], 16;\n" :: "r"(da + 16), "l"(Ag + k0 + 4));
            asm volatile("cp.async.cg.shared.global [%0], [%1], 16;\n" :: "r"(db),      "l"(Bg + k0));
            asm volatile("cp.async.cg.shared.global [%0], [%1], 16;\n" :: "r"(db + 16), "l"(Bg + k0 + 4));
            asm volatile("cp.async.commit_group;\n");
        }

        const float* pa = As[it & 1];
        const float* pb = Bs[it & 1];

        #pragma unroll
        for (int ks = 0; ks < 16; ks += 8) {
            unsigned a[2][4];
            #pragma unroll
            for (int mi = 0; mi < 2; mi++) {
                const int r = wm + mi * 16;
                a[mi][0] = f2tf(pa[(r + g    ) * LDST + ks + l4    ]);
                a[mi][1] = f2tf(pa[(r + g + 8) * LDST + ks + l4    ]);
                a[mi][2] = f2tf(pa[(r + g    ) * LDST + ks + l4 + 4]);
                a[mi][3] = f2tf(pa[(r + g + 8) * LDST + ks + l4 + 4]);
            }
            unsigned b[8][2];
            #pragma unroll
            for (int ni = 0; ni < 8; ni++) {
                const int c = wn + ni * 8;
                b[ni][0] = f2tf(pb[(c + g) * LDST + ks + l4    ]);
                b[ni][1] = f2tf(pb[(c + g) * LDST + ks + l4 + 4]);
            }
            #pragma unroll
            for (int mi = 0; mi < 2; mi++)
                #pragma unroll
                for (int ni = 0; ni < 8; ni++)
                    mma1688(acc[mi][ni], a[mi], b[ni]);
        }
    }

    // epilogue: c0,c1 -> row g, cols 2*l4, 2*l4+1 ; c2,c3 -> row g+8
    #pragma unroll
    for (int mi = 0; mi < 2; mi++) {
        #pragma unroll
        for (int ni = 0; ni < 8; ni++) {
            const int r0 = bm + wm + mi * 16 + g;
            const int c0 = bn + wn + ni * 8 + l4 * 2;
            *(float2*)&C[(size_t)r0 * N + c0]       = make_float2(acc[mi][ni][0], acc[mi][ni][1]);
            *(float2*)&C[(size_t)(r0 + 8) * N + c0] = make_float2(acc[mi][ni][2], acc[mi][ni][3]);
        }
    }
}

// ============================================================
// RoPE + transpose to [b][h][s][d]
// ============================================================
__global__ void rope_q_kernel(const float* __restrict__ qf,
                              const float* __restrict__ fc,
                              const float* __restrict__ fs,
                              float* __restrict__ qo) {
    int idx = blockIdx.x * blockDim.x + threadIdx.x;   // MR*NH*64
    int p   = idx & 63;
    int h   = (idx >> 6) & (NH - 1);
    int row = idx >> 11;                   // b*SS+s
    int s   = row & (SS - 1);
    int b   = row >> 11;
    float2 tv = *(const float2*)&qf[(size_t)row * DIM + h * HD + 2 * p];
    float c = fc[s * 64 + p], sn = fs[s * 64 + p];
    float2 o = make_float2(tv.x * c - tv.y * sn, tv.x * sn + tv.y * c);
    *(float2*)&qo[(((size_t)(b * NH + h)) * SS + s) * HD + 2 * p] = o;
}

__global__ void rope_k_kernel(const float* __restrict__ kf,
                              const float* __restrict__ fc,
                              const float* __restrict__ fs,
                              float* __restrict__ ko) {
    int idx = blockIdx.x * blockDim.x + threadIdx.x;   // MR*NKV*64
    int p   = idx & 63;
    int h   = (idx >> 6) & (NKV - 1);
    int row = idx >> 9;
    int s   = row & (SS - 1);
    int b   = row >> 11;
    float2 tv = *(const float2*)&kf[(size_t)row * KVDIM + h * HD + 2 * p];
    float c = fc[s * 64 + p], sn = fs[s * 64 + p];
    float2 o = make_float2(tv.x * c - tv.y * sn, tv.x * sn + tv.y * c);
    *(float2*)&ko[(((size_t)(b * NKV + h)) * SS + s) * HD + 2 * p] = o;
}

__global__ void v_tr_kernel(const float* __restrict__ vf, float* __restrict__ vo) {
    int idx = blockIdx.x * blockDim.x + threadIdx.x;   // MR*KVDIM/4 float4s
    int d4  = idx & 31;
    int h   = (idx >> 5) & (NKV - 1);
    int row = idx >> 8;
    int s   = row & (SS - 1);
    int b   = row >> 11;
    float4 v = ((const float4*)vf)[idx];
    ((float4*)vo)[(((size_t)(b * NKV + h)) * SS + s) * (HD / 4) + d4] = v;
}

// ============================================================
// Flash attention fp32 (unchanged from R1)
// ============================================================
__global__ void attn_kernel(const float* __restrict__ Q, const float* __restrict__ Kt,
                            const float* __restrict__ Vt, float* __restrict__ O) {
    __shared__ float Qs[32][132];
    __shared__ float KVs[32][132];
    const int qt = blockIdx.x, h = blockIdx.y, b = blockIdx.z;
    const int kvh = h >> 2;
    const int q0 = qt * 32;
    const float* qbase = Q  + (((size_t)(b * NH  + h  )) * SS + q0) * HD;
    const float* kbase = Kt + (((size_t)(b * NKV + kvh)) * SS) * HD;
    const float* vbase = Vt + (((size_t)(b * NKV + kvh)) * SS) * HD;
    const int t = threadIdx.x;
    const int m = t >> 3, oct = t & 7;

    for (int i = t; i < 1024; i += 256) {
        int r = i >> 5, c = i & 31;
        *(float4*)&Qs[r][c << 2] = ((const float4*)qbase)[i];
    }

    float mx = -INFINITY, l = 0.f;
    float acc[16];
    #pragma unroll
    for (int j = 0; j < 16; j++) acc[j] = 0.f;
    const float scale = 0.08838834764831845f;  // 1/sqrt(128)

    for (int k0 = 0; k0 <= q0; k0 += 32) {
        __syncthreads();
        for (int i = t; i < 1024; i += 256) {
            int r = i >> 5, c = i & 31;
            *(float4*)&KVs[r][c << 2] = ((const float4*)(kbase + (size_t)k0 * HD))[i];
        }
        __syncthreads();

        float s0 = 0, s1 = 0, s2 = 0, s3 = 0;
        #pragma unroll 8
        for (int d4 = 0; d4 < 32; d4++) {
            float4 qv  = *(const float4*)&Qs[m][d4 << 2];
            float4 k0v = *(const float4*)&KVs[oct     ][d4 << 2];
            float4 k1v = *(const float4*)&KVs[oct +  8][d4 << 2];
            float4 k2v = *(const float4*)&KVs[oct + 16][d4 << 2];
            float4 k3v = *(const float4*)&KVs[oct + 24][d4 << 2];
            s0 += qv.x*k0v.x + qv.y*k0v.y + qv.z*k0v.z + qv.w*k0v.w;
            s1 += qv.x*k1v.x + qv.y*k1v.y + qv.z*k1v.z + qv.w*k1v.w;
            s2 += qv.x*k2v.x + qv.y*k2v.y + qv.z*k2v.z + qv.w*k2v.w;
            s3 += qv.x*k3v.x + qv.y*k3v.y + qv.z*k3v.z + qv.w*k3v.w;
        }
        s0 *= scale; s1 *= scale; s2 *= scale; s3 *= scale;
        if (k0 == q0) {
            int qg = q0 + m;
            if (k0 + oct      > qg) s0 = -1e30f;
            if (k0 + oct +  8 > qg) s1 = -1e30f;
            if (k0 + oct + 16 > qg) s2 = -1e30f;
            if (k0 + oct + 24 > qg) s3 = -1e30f;
        }
        float tm = fmaxf(fmaxf(s0, s1), fmaxf(s2, s3));
        #pragma unroll
        for (int o = 1; o < 8; o <<= 1)
            tm = fmaxf(tm, __shfl_xor_sync(0xffffffffu, tm, o));
        float mn = fmaxf(mx, tm);
        float p0 = __expf(s0 - mn), p1 = __expf(s1 - mn);
        float p2 = __expf(s2 - mn), p3 = __expf(s3 - mn);
        float ls = p0 + p1 + p2 + p3;
        #pragma unroll
        for (int o = 1; o < 8; o <<= 1)
            ls += __shfl_xor_sync(0xffffffffu, ls, o);
        float csc = __expf(mx - mn);
        l = l * csc + ls;
        mx = mn;
        #pragma unroll
        for (int j = 0; j < 16; j++) acc[j] *= csc;

        __syncthreads();
        for (int i = t; i < 1024; i += 256) {
            int r = i >> 5, c = i & 31;
            *(float4*)&KVs[r][c << 2] = ((const float4*)(vbase + (size_t)k0 * HD))[i];
        }
        __syncthreads();

        float pr[4] = {p0, p1, p2, p3};
        #pragma unroll
        for (int kk = 0; kk < 32; kk++) {
            float p = __shfl_sync(0xffffffffu, pr[kk >> 3], kk & 7, 8);
            #pragma unroll
            for (int jj = 0; jj < 16; jj++)
                acc[jj] += p * KVs[kk][oct + (jj << 3)];
        }
    }

    float inv = 1.f / l;
    float* orow = O + ((size_t)(b * SS) + q0 + m) * DIM + h * HD;
    #pragma unroll
    for (int jj = 0; jj < 16; jj++)
        orow[oct + (jj << 3)] = acc[jj] * inv;
}

// ============================================================
extern "C" void kernel_launch(void* const* d_in, const int* in_sizes, int n_in,
                              void* d_out, int out_size) {
    const float* x  = (const float*)d_in[0];
    const float* wq = (const float*)d_in[1];
    const float* wk = (const float*)d_in[2];
    const float* wv = (const float*)d_in[3];
    const float* wo = (const float*)d_in[4];
    const float* fc = (const float*)d_in[5];
    const float* fs = (const float*)d_in[6];
    float* out = (float*)d_out;

    float *qf, *kf, *vf, *q, *k, *v, *at;
    cudaGetSymbolAddress((void**)&qf, g_qf);
    cudaGetSymbolAddress((void**)&kf, g_kf);
    cudaGetSymbolAddress((void**)&vf, g_vf);
    cudaGetSymbolAddress((void**)&q,  g_q);
    cudaGetSymbolAddress((void**)&k,  g_k);
    cudaGetSymbolAddress((void**)&v,  g_v);
    cudaGetSymbolAddress((void**)&at, g_at);

    // QKV projections (tf32 tensor cores)
    gemm_nt_tf32<<<dim3(DIM   / 128, MR / 128), 256>>>(x, wq, qf, MR, DIM,   DIM);
    gemm_nt_tf32<<<dim3(KVDIM / 128, MR / 128), 256>>>(x, wk, kf, MR, KVDIM, DIM);
    gemm_nt_tf32<<<dim3(KVDIM / 128, MR / 128), 256>>>(x, wv, vf, MR, KVDIM, DIM);

    // RoPE + layout transforms
    rope_q_kernel<<<(MR * NH  * 64) / 256, 256>>>(qf, fc, fs, q);
    rope_k_kernel<<<(MR * NKV * 64) / 256, 256>>>(kf, fc, fs, k);
    v_tr_kernel  <<<(MR * KVDIM / 4) / 256, 256>>>(vf, v);

    // causal GQA attention
    attn_kernel<<<dim3(SS / 32, NH, BB), 256>>>(q, k, v, at);

    // output projection (tf32 tensor cores)
    gemm_nt_tf32<<<dim3(DIM / 128, MR / 128), 256>>>(at, wo, out, MR, DIM, DIM);
}

// round 7
// speedup vs baseline: 2.3556x; 1.2428x over previous
#include <cuda_runtime.h>
#include <cuda_fp16.h>
#include <math.h>
#include <cstdint>

#define BB 2
#define SS 2048
#define DIM 4096
#define NH 32
#define NKV 8
#define HD 128
#define MR (BB*SS)          // 4096 rows
#define KVDIM (NKV*HD)      // 1024

// ---- scratch (device globals; no allocation allowed) ----
__device__ float  g_qf[(size_t)MR * DIM];     // Q proj fp32
__device__ float  g_kf[(size_t)MR * KVDIM];
__device__ float  g_vf[(size_t)MR * KVDIM];
__device__ float  g_q [(size_t)MR * DIM];     // [b][h][s][d]
__device__ float  g_k [(size_t)MR * KVDIM];   // [b][kvh][s][d]
__device__ float  g_v [(size_t)MR * KVDIM];
__device__ __half g_ath[(size_t)MR * DIM];    // attn out (fp16), [row][h*128+d]
__device__ __half g_xh [(size_t)MR * DIM];    // fp16 copies of inputs
__device__ __half g_wqh[(size_t)DIM * DIM];
__device__ __half g_wkh[(size_t)KVDIM * DIM];
__device__ __half g_wvh[(size_t)KVDIM * DIM];
__device__ __half g_woh[(size_t)DIM * DIM];

// ============================================================
// fp32 -> fp16 convert
// ============================================================
__global__ void cvt_h(const float* __restrict__ in, __half* __restrict__ out, int n2) {
    int i = blockIdx.x * blockDim.x + threadIdx.x;
    if (i < n2) {
        float2 v = ((const float2*)in)[i];
        ((__half2*)out)[i] = __floats2half2_rn(v.x, v.y);
    }
}

// ============================================================
// fp16 HMMA NT GEMM: C[M,N] = A[M,K] * B[N,K]^T (fp16 in, fp32 acc/out)
// BM=BN=128, BK=32, 256 threads (8 warps 4Mx2N), warp tile 32x64.
// mma.sync.m16n8k16 + ldmatrix.x4; smem rows padded to 40 halves (80B).
// ldmatrix.x4 register order is {r0:(g0,k0) r1:(g1,k0) r2:(g0,k1) r3:(g1,k1)}
// (g = 8-row group, k = 8-col half). A consumes {r0,r1,r2,r3} directly;
// B must be regrouped: {r0,r2} for n-group 0, {r1,r3} for n-group 1.
// ============================================================
#define LDH 40   // halves per smem row (32 data + 8 pad)

__device__ __forceinline__ uint32_t smem_u32(const void* p) {
    uint32_t a;
    asm("{ .reg .u64 t; cvta.to.shared.u64 t, %1; cvt.u32.u64 %0, t; }" : "=r"(a) : "l"(p));
    return a;
}

__device__ __forceinline__ void ldsm4(uint32_t* r, uint32_t addr) {
    asm volatile("ldmatrix.sync.aligned.m8n8.x4.shared.b16 {%0,%1,%2,%3}, [%4];"
                 : "=r"(r[0]), "=r"(r[1]), "=r"(r[2]), "=r"(r[3]) : "r"(addr));
}

__device__ __forceinline__ void mma16816(float* c, const uint32_t* a,
                                         uint32_t b0, uint32_t b1) {
    asm volatile(
        "mma.sync.aligned.m16n8k16.row.col.f32.f16.f16.f32 "
        "{%0,%1,%2,%3}, {%4,%5,%6,%7}, {%8,%9}, {%0,%1,%2,%3};\n"
        : "+f"(c[0]), "+f"(c[1]), "+f"(c[2]), "+f"(c[3])
        : "r"(a[0]), "r"(a[1]), "r"(a[2]), "r"(a[3]), "r"(b0), "r"(b1));
}

__global__ __launch_bounds__(256, 2)
void gemm_nt_h16(const __half* __restrict__ A, const __half* __restrict__ Bw,
                 float* __restrict__ C, int M, int N, int K) {
    __shared__ __half As[2][128 * LDH];
    __shared__ __half Bs[2][128 * LDH];
    const int t = threadIdx.x;
    const int bm = blockIdx.y * 128, bn = blockIdx.x * 128;
    const int lane = t & 31, warp = t >> 5;
    const int wm = (warp >> 1) * 32, wn = (warp & 1) * 64;

    // loader mapping: 512 16B chunks per tile, 2 per thread
    const int r0 = t >> 2, c0 = t & 3;
    const int r1 = (t + 256) >> 2;
    const __half* Ag = A  + (size_t)bm * K;
    const __half* Bg = Bw + (size_t)bn * K;

    const uint32_t sa[2] = { smem_u32(&As[0][0]), smem_u32(&As[1][0]) };
    const uint32_t sb[2] = { smem_u32(&Bs[0][0]), smem_u32(&Bs[1][0]) };

#define FILLT(buf, kt) do {                                                        \
    uint32_t _a = sa[buf], _b = sb[buf];                                           \
    const __half* _Ak = Ag + (kt) * 32;                                            \
    const __half* _Bk = Bg + (kt) * 32;                                            \
    asm volatile("cp.async.cg.shared.global [%0], [%1], 16;"                       \
        :: "r"(_a + (r0 * LDH + c0 * 8) * 2), "l"(_Ak + (size_t)r0 * K + c0 * 8)); \
    asm volatile("cp.async.cg.shared.global [%0], [%1], 16;"                       \
        :: "r"(_a + (r1 * LDH + c0 * 8) * 2), "l"(_Ak + (size_t)r1 * K + c0 * 8)); \
    asm volatile("cp.async.cg.shared.global [%0], [%1], 16;"                       \
        :: "r"(_b + (r0 * LDH + c0 * 8) * 2), "l"(_Bk + (size_t)r0 * K + c0 * 8)); \
    asm volatile("cp.async.cg.shared.global [%0], [%1], 16;"                       \
        :: "r"(_b + (r1 * LDH + c0 * 8) * 2), "l"(_Bk + (size_t)r1 * K + c0 * 8)); \
    asm volatile("cp.async.commit_group;"); } while (0)

    float acc[2][8][4];
    #pragma unroll
    for (int mi = 0; mi < 2; mi++)
        #pragma unroll
        for (int ni = 0; ni < 8; ni++)
            #pragma unroll
            for (int j = 0; j < 4; j++) acc[mi][ni][j] = 0.f;

    const int niter = K >> 5;
    FILLT(0, 0);

    for (int it = 0; it < niter; it++) {
        const int buf = it & 1;
        asm volatile("cp.async.wait_group 0;");
        __syncthreads();
        if (it + 1 < niter) FILLT(buf ^ 1, it + 1);

        const uint32_t pa = sa[buf], pb = sb[buf];

        #pragma unroll
        for (int ks = 0; ks < 2; ks++) {          // two k16 steps
            uint32_t a[2][4];
            #pragma unroll
            for (int mi = 0; mi < 2; mi++) {
                uint32_t addr = pa + (((wm + mi * 16 + (lane & 15)) * LDH) +
                                      (2 * ks + (lane >> 4)) * 8) * 2;
                ldsm4(a[mi], addr);
            }
            uint32_t b[4][4];
            #pragma unroll
            for (int np = 0; np < 4; np++) {
                uint32_t addr = pb + (((wn + np * 16 + (lane & 15)) * LDH) +
                                      (2 * ks + (lane >> 4)) * 8) * 2;
                ldsm4(b[np], addr);
            }
            #pragma unroll
            for (int mi = 0; mi < 2; mi++)
                #pragma unroll
                for (int np = 0; np < 4; np++) {
                    // n-group 0 of this 16-col block: k-halves are r0, r2
                    mma16816(acc[mi][np * 2],     a[mi], b[np][0], b[np][2]);
                    // n-group 1: k-halves are r1, r3
                    mma16816(acc[mi][np * 2 + 1], a[mi], b[np][1], b[np][3]);
                }
        }
        __syncthreads();
    }

    const int g = lane >> 2, l4 = lane & 3;
    #pragma unroll
    for (int mi = 0; mi < 2; mi++) {
        #pragma unroll
        for (int ni = 0; ni < 8; ni++) {
            const int rr = bm + wm + mi * 16 + g;
            const int cc = bn + wn + ni * 8 + l4 * 2;
            *(float2*)&C[(size_t)rr * N + cc]       = make_float2(acc[mi][ni][0], acc[mi][ni][1]);
            *(float2*)&C[(size_t)(rr + 8) * N + cc] = make_float2(acc[mi][ni][2], acc[mi][ni][3]);
        }
    }
}

// ============================================================
// RoPE + transpose to [b][h][s][d]
// ============================================================
__global__ void rope_q_kernel(const float* __restrict__ qf,
                              const float* __restrict__ fc,
                              const float* __restrict__ fs,
                              float* __restrict__ qo) {
    int idx = blockIdx.x * blockDim.x + threadIdx.x;
    int p   = idx & 63;
    int h   = (idx >> 6) & (NH - 1);
    int row = idx >> 11;
    int s   = row & (SS - 1);
    int b   = row >> 11;
    float2 tv = *(const float2*)&qf[(size_t)row * DIM + h * HD + 2 * p];
    float c = fc[s * 64 + p], sn = fs[s * 64 + p];
    float2 o = make_float2(tv.x * c - tv.y * sn, tv.x * sn + tv.y * c);
    *(float2*)&qo[(((size_t)(b * NH + h)) * SS + s) * HD + 2 * p] = o;
}

__global__ void rope_k_kernel(const float* __restrict__ kf,
                              const float* __restrict__ fc,
                              const float* __restrict__ fs,
                              float* __restrict__ ko) {
    int idx = blockIdx.x * blockDim.x + threadIdx.x;
    int p   = idx & 63;
    int h   = (idx >> 6) & (NKV - 1);
    int row = idx >> 9;
    int s   = row & (SS - 1);
    int b   = row >> 11;
    float2 tv = *(const float2*)&kf[(size_t)row * KVDIM + h * HD + 2 * p];
    float c = fc[s * 64 + p], sn = fs[s * 64 + p];
    float2 o = make_float2(tv.x * c - tv.y * sn, tv.x * sn + tv.y * c);
    *(float2*)&ko[(((size_t)(b * NKV + h)) * SS + s) * HD + 2 * p] = o;
}

__global__ void v_tr_kernel(const float* __restrict__ vf, float* __restrict__ vo) {
    int idx = blockIdx.x * blockDim.x + threadIdx.x;
    int d4  = idx & 31;
    int h   = (idx >> 5) & (NKV - 1);
    int row = idx >> 8;
    int s   = row & (SS - 1);
    int b   = row >> 11;
    float4 v = ((const float4*)vf)[idx];
    ((float4*)vo)[(((size_t)(b * NKV + h)) * SS + s) * (HD / 4) + d4] = v;
}

// ============================================================
// Flash attention fp32 (epilogue writes fp16 for the wo GEMM)
// ============================================================
__global__ void attn_kernel(const float* __restrict__ Q, const float* __restrict__ Kt,
                            const float* __restrict__ Vt, __half* __restrict__ O) {
    __shared__ float Qs[32][132];
    __shared__ float KVs[32][132];
    const int qt = blockIdx.x, h = blockIdx.y, b = blockIdx.z;
    const int kvh = h >> 2;
    const int q0 = qt * 32;
    const float* qbase = Q  + (((size_t)(b * NH  + h  )) * SS + q0) * HD;
    const float* kbase = Kt + (((size_t)(b * NKV + kvh)) * SS) * HD;
    const float* vbase = Vt + (((size_t)(b * NKV + kvh)) * SS) * HD;
    const int t = threadIdx.x;
    const int m = t >> 3, oct = t & 7;

    for (int i = t; i < 1024; i += 256) {
        int r = i >> 5, c = i & 31;
        *(float4*)&Qs[r][c << 2] = ((const float4*)qbase)[i];
    }

    float mx = -INFINITY, l = 0.f;
    float acc[16];
    #pragma unroll
    for (int j = 0; j < 16; j++) acc[j] = 0.f;
    const float scale = 0.08838834764831845f;

    for (int k0 = 0; k0 <= q0; k0 += 32) {
        __syncthreads();
        for (int i = t; i < 1024; i += 256) {
            int r = i >> 5, c = i & 31;
            *(float4*)&KVs[r][c << 2] = ((const float4*)(kbase + (size_t)k0 * HD))[i];
        }
        __syncthreads();

        float s0 = 0, s1 = 0, s2 = 0, s3 = 0;
        #pragma unroll 8
        for (int d4 = 0; d4 < 32; d4++) {
            float4 qv  = *(const float4*)&Qs[m][d4 << 2];
            float4 k0v = *(const float4*)&KVs[oct     ][d4 << 2];
            float4 k1v = *(const float4*)&KVs[oct +  8][d4 << 2];
            float4 k2v = *(const float4*)&KVs[oct + 16][d4 << 2];
            float4 k3v = *(const float4*)&KVs[oct + 24][d4 << 2];
            s0 += qv.x*k0v.x + qv.y*k0v.y + qv.z*k0v.z + qv.w*k0v.w;
            s1 += qv.x*k1v.x + qv.y*k1v.y + qv.z*k1v.z + qv.w*k1v.w;
            s2 += qv.x*k2v.x + qv.y*k2v.y + qv.z*k2v.z + qv.w*k2v.w;
            s3 += qv.x*k3v.x + qv.y*k3v.y + qv.z*k3v.z + qv.w*k3v.w;
        }
        s0 *= scale; s1 *= scale; s2 *= scale; s3 *= scale;
        if (k0 == q0) {
            int qg = q0 + m;
            if (k0 + oct      > qg) s0 = -1e30f;
            if (k0 + oct +  8 > qg) s1 = -1e30f;
            if (k0 + oct + 16 > qg) s2 = -1e30f;
            if (k0 + oct + 24 > qg) s3 = -1e30f;
        }
        float tm = fmaxf(fmaxf(s0, s1), fmaxf(s2, s3));
        #pragma unroll
        for (int o = 1; o < 8; o <<= 1)
            tm = fmaxf(tm, __shfl_xor_sync(0xffffffffu, tm, o));
        float mn = fmaxf(mx, tm);
        float p0 = __expf(s0 - mn), p1 = __expf(s1 - mn);
        float p2 = __expf(s2 - mn), p3 = __expf(s3 - mn);
        float ls = p0 + p1 + p2 + p3;
        #pragma unroll
        for (int o = 1; o < 8; o <<= 1)
            ls += __shfl_xor_sync(0xffffffffu, ls, o);
        float csc = __expf(mx - mn);
        l = l * csc + ls;
        mx = mn;
        #pragma unroll
        for (int j = 0; j < 16; j++) acc[j] *= csc;

        __syncthreads();
        for (int i = t; i < 1024; i += 256) {
            int r = i >> 5, c = i & 31;
            *(float4*)&KVs[r][c << 2] = ((const float4*)(vbase + (size_t)k0 * HD))[i];
        }
        __syncthreads();

        float pr[4] = {p0, p1, p2, p3};
        #pragma unroll
        for (int kk = 0; kk < 32; kk++) {
            float p = __shfl_sync(0xffffffffu, pr[kk >> 3], kk & 7, 8);
            #pragma unroll
            for (int jj = 0; jj < 16; jj++)
                acc[jj] += p * KVs[kk][oct + (jj << 3)];
        }
    }

    float inv = 1.f / l;
    __half* orow = O + ((size_t)(b * SS) + q0 + m) * DIM + h * HD;
    #pragma unroll
    for (int jj = 0; jj < 16; jj++)
        orow[oct + (jj << 3)] = __float2half(acc[jj] * inv);
}

// ============================================================
extern "C" void kernel_launch(void* const* d_in, const int* in_sizes, int n_in,
                              void* d_out, int out_size) {
    const float* x  = (const float*)d_in[0];
    const float* wq = (const float*)d_in[1];
    const float* wk = (const float*)d_in[2];
    const float* wv = (const float*)d_in[3];
    const float* wo = (const float*)d_in[4];
    const float* fc = (const float*)d_in[5];
    const float* fs = (const float*)d_in[6];
    float* out = (float*)d_out;

    float *qf, *kf, *vf, *q, *k, *v;
    __half *ath, *xh, *wqh, *wkh, *wvh, *woh;
    cudaGetSymbolAddress((void**)&qf,  g_qf);
    cudaGetSymbolAddress((void**)&kf,  g_kf);
    cudaGetSymbolAddress((void**)&vf,  g_vf);
    cudaGetSymbolAddress((void**)&q,   g_q);
    cudaGetSymbolAddress((void**)&k,   g_k);
    cudaGetSymbolAddress((void**)&v,   g_v);
    cudaGetSymbolAddress((void**)&ath, g_ath);
    cudaGetSymbolAddress((void**)&xh,  g_xh);
    cudaGetSymbolAddress((void**)&wqh, g_wqh);
    cudaGetSymbolAddress((void**)&wkh, g_wkh);
    cudaGetSymbolAddress((void**)&wvh, g_wvh);
    cudaGetSymbolAddress((void**)&woh, g_woh);

    // fp16 copies
    cvt_h<<<(MR * DIM / 2 + 255) / 256, 256>>>(x,  xh,  MR * DIM / 2);
    cvt_h<<<((size_t)DIM * DIM / 2 + 255) / 256, 256>>>(wq, wqh, DIM * DIM / 2);
    cvt_h<<<((size_t)KVDIM * DIM / 2 + 255) / 256, 256>>>(wk, wkh, KVDIM * DIM / 2);
    cvt_h<<<((size_t)KVDIM * DIM / 2 + 255) / 256, 256>>>(wv, wvh, KVDIM * DIM / 2);
    cvt_h<<<((size_t)DIM * DIM / 2 + 255) / 256, 256>>>(wo, woh, DIM * DIM / 2);

    // QKV projections (fp16 HMMA)
    gemm_nt_h16<<<dim3(DIM / 128,   MR / 128), 256>>>(xh, wqh, qf, MR, DIM,   DIM);
    gemm_nt_h16<<<dim3(KVDIM / 128, MR / 128), 256>>>(xh, wkh, kf, MR, KVDIM, DIM);
    gemm_nt_h16<<<dim3(KVDIM / 128, MR / 128), 256>>>(xh, wvh, vf, MR, KVDIM, DIM);

    // RoPE + layout transforms
    rope_q_kernel<<<(MR * NH  * 64) / 256, 256>>>(qf, fc, fs, q);
    rope_k_kernel<<<(MR * NKV * 64) / 256, 256>>>(kf, fc, fs, k);
    v_tr_kernel  <<<(MR * KVDIM / 4) / 256, 256>>>(vf, v);

    // causal GQA attention (fp32 math, fp16 output)
    attn_kernel<<<dim3(SS / 32, NH, BB), 256>>>(q, k, v, ath);

    // output projection (fp16 HMMA)
    gemm_nt_h16<<<dim3(DIM / 128, MR / 128), 256>>>(ath, woh, out, MR, DIM, DIM);
}

// round 8
// speedup vs baseline: 8.8714x; 3.7661x over previous
#include <cuda_runtime.h>
#include <cuda_fp16.h>
#include <math.h>
#include <cstdint>

#define BB 2
#define SS 2048
#define DIM 4096
#define NH 32
#define NKV 8
#define HD 128
#define MR (BB*SS)          // 4096 rows
#define KVDIM (NKV*HD)      // 1024
#define SCALE 0.08838834764831845f   // 1/sqrt(128)

// ---- scratch (device globals; no allocation allowed) ----
__device__ float  g_qf[(size_t)MR * DIM];     // Q proj fp32
__device__ float  g_kf[(size_t)MR * KVDIM];
__device__ float  g_vf[(size_t)MR * KVDIM];
__device__ __half g_qh[(size_t)MR * DIM];     // roped Q fp16 [b][h][s][d] (pre-scaled)
__device__ __half g_kh[(size_t)MR * KVDIM];   // roped K fp16 [b][kvh][s][d]
__device__ __half g_vh[(size_t)MR * KVDIM];   // V fp16 [b][kvh][s][d]
__device__ __half g_ath[(size_t)MR * DIM];    // attn out fp16 [row][h*128+d]
__device__ __half g_xh [(size_t)MR * DIM];    // fp16 copies of inputs
__device__ __half g_wqh[(size_t)DIM * DIM];
__device__ __half g_wkh[(size_t)KVDIM * DIM];
__device__ __half g_wvh[(size_t)KVDIM * DIM];
__device__ __half g_woh[(size_t)DIM * DIM];

// ============================================================
// helpers
// ============================================================
__device__ __forceinline__ uint32_t smem_u32(const void* p) {
    uint32_t a;
    asm("{ .reg .u64 t; cvta.to.shared.u64 t, %1; cvt.u32.u64 %0, t; }" : "=r"(a) : "l"(p));
    return a;
}
__device__ __forceinline__ void cpa16(uint32_t dst, const void* src) {
    asm volatile("cp.async.cg.shared.global [%0], [%1], 16;" :: "r"(dst), "l"(src));
}
#define CP_COMMIT asm volatile("cp.async.commit_group;")
#define CP_WAIT0  asm volatile("cp.async.wait_group 0;")
#define CP_WAIT1  asm volatile("cp.async.wait_group 1;")

__device__ __forceinline__ void ldsm4(uint32_t* r, uint32_t addr) {
    asm volatile("ldmatrix.sync.aligned.m8n8.x4.shared.b16 {%0,%1,%2,%3}, [%4];"
                 : "=r"(r[0]), "=r"(r[1]), "=r"(r[2]), "=r"(r[3]) : "r"(addr));
}
__device__ __forceinline__ void ldsm4t(uint32_t* r, uint32_t addr) {
    asm volatile("ldmatrix.sync.aligned.m8n8.x4.trans.shared.b16 {%0,%1,%2,%3}, [%4];"
                 : "=r"(r[0]), "=r"(r[1]), "=r"(r[2]), "=r"(r[3]) : "r"(addr));
}
__device__ __forceinline__ void mma16816(float* c, const uint32_t* a,
                                         uint32_t b0, uint32_t b1) {
    asm volatile(
        "mma.sync.aligned.m16n8k16.row.col.f32.f16.f16.f32 "
        "{%0,%1,%2,%3}, {%4,%5,%6,%7}, {%8,%9}, {%0,%1,%2,%3};\n"
        : "+f"(c[0]), "+f"(c[1]), "+f"(c[2]), "+f"(c[3])
        : "r"(a[0]), "r"(a[1]), "r"(a[2]), "r"(a[3]), "r"(b0), "r"(b1));
}
__device__ __forceinline__ uint32_t packh2(float a, float b) {
    __half2 h = __floats2half2_rn(a, b);
    return *(uint32_t*)&h;
}

// ============================================================
// fp32 -> fp16 convert
// ============================================================
__global__ void cvt_h(const float* __restrict__ in, __half* __restrict__ out, int n2) {
    int i = blockIdx.x * blockDim.x + threadIdx.x;
    if (i < n2) {
        float2 v = ((const float2*)in)[i];
        ((__half2*)out)[i] = __floats2half2_rn(v.x, v.y);
    }
}

// ============================================================
// fp16 HMMA NT GEMM (unchanged from R7, passing)
// ============================================================
#define LDH 40

__global__ __launch_bounds__(256, 2)
void gemm_nt_h16(const __half* __restrict__ A, const __half* __restrict__ Bw,
                 float* __restrict__ C, int M, int N, int K) {
    __shared__ __half As[2][128 * LDH];
    __shared__ __half Bs[2][128 * LDH];
    const int t = threadIdx.x;
    const int bm = blockIdx.y * 128, bn = blockIdx.x * 128;
    const int lane = t & 31, warp = t >> 5;
    const int wm = (warp >> 1) * 32, wn = (warp & 1) * 64;

    const int r0 = t >> 2, c0 = t & 3;
    const int r1 = (t + 256) >> 2;
    const __half* Ag = A  + (size_t)bm * K;
    const __half* Bg = Bw + (size_t)bn * K;

    const uint32_t sa[2] = { smem_u32(&As[0][0]), smem_u32(&As[1][0]) };
    const uint32_t sb[2] = { smem_u32(&Bs[0][0]), smem_u32(&Bs[1][0]) };

#define FILLT(buf, kt) do {                                                        \
    uint32_t _a = sa[buf], _b = sb[buf];                                           \
    const __half* _Ak = Ag + (kt) * 32;                                            \
    const __half* _Bk = Bg + (kt) * 32;                                            \
    cpa16(_a + (r0 * LDH + c0 * 8) * 2, _Ak + (size_t)r0 * K + c0 * 8);            \
    cpa16(_a + (r1 * LDH + c0 * 8) * 2, _Ak + (size_t)r1 * K + c0 * 8);            \
    cpa16(_b + (r0 * LDH + c0 * 8) * 2, _Bk + (size_t)r0 * K + c0 * 8);            \
    cpa16(_b + (r1 * LDH + c0 * 8) * 2, _Bk + (size_t)r1 * K + c0 * 8);            \
    CP_COMMIT; } while (0)

    float acc[2][8][4];
    #pragma unroll
    for (int mi = 0; mi < 2; mi++)
        #pragma unroll
        for (int ni = 0; ni < 8; ni++)
            #pragma unroll
            for (int j = 0; j < 4; j++) acc[mi][ni][j] = 0.f;

    const int niter = K >> 5;
    FILLT(0, 0);

    for (int it = 0; it < niter; it++) {
        const int buf = it & 1;
        CP_WAIT0;
        __syncthreads();
        if (it + 1 < niter) FILLT(buf ^ 1, it + 1);

        const uint32_t pa = sa[buf], pb = sb[buf];

        #pragma unroll
        for (int ks = 0; ks < 2; ks++) {
            uint32_t a[2][4];
            #pragma unroll
            for (int mi = 0; mi < 2; mi++) {
                uint32_t addr = pa + (((wm + mi * 16 + (lane & 15)) * LDH) +
                                      (2 * ks + (lane >> 4)) * 8) * 2;
                ldsm4(a[mi], addr);
            }
            uint32_t b[4][4];
            #pragma unroll
            for (int np = 0; np < 4; np++) {
                uint32_t addr = pb + (((wn + np * 16 + (lane & 15)) * LDH) +
                                      (2 * ks + (lane >> 4)) * 8) * 2;
                ldsm4(b[np], addr);
            }
            #pragma unroll
            for (int mi = 0; mi < 2; mi++)
                #pragma unroll
                for (int np = 0; np < 4; np++) {
                    mma16816(acc[mi][np * 2],     a[mi], b[np][0], b[np][2]);
                    mma16816(acc[mi][np * 2 + 1], a[mi], b[np][1], b[np][3]);
                }
        }
        __syncthreads();
    }

    const int g = lane >> 2, l4 = lane & 3;
    #pragma unroll
    for (int mi = 0; mi < 2; mi++) {
        #pragma unroll
        for (int ni = 0; ni < 8; ni++) {
            const int rr = bm + wm + mi * 16 + g;
            const int cc = bn + wn + ni * 8 + l4 * 2;
            *(float2*)&C[(size_t)rr * N + cc]       = make_float2(acc[mi][ni][0], acc[mi][ni][1]);
            *(float2*)&C[(size_t)(rr + 8) * N + cc] = make_float2(acc[mi][ni][2], acc[mi][ni][3]);
        }
    }
}

// ============================================================
// RoPE + transpose, fp16 output. Q is pre-scaled by 1/sqrt(128).
// ============================================================
__global__ void rope_q_kernel(const float* __restrict__ qf,
                              const float* __restrict__ fc,
                              const float* __restrict__ fs,
                              __half* __restrict__ qo) {
    int idx = blockIdx.x * blockDim.x + threadIdx.x;
    int p   = idx & 63;
    int h   = (idx >> 6) & (NH - 1);
    int row = idx >> 11;
    int s   = row & (SS - 1);
    int b   = row >> 11;
    float2 tv = *(const float2*)&qf[(size_t)row * DIM + h * HD + 2 * p];
    float c = fc[s * 64 + p], sn = fs[s * 64 + p];
    float x0 = (tv.x * c - tv.y * sn) * SCALE;
    float x1 = (tv.x * sn + tv.y * c) * SCALE;
    *(__half2*)&qo[(((size_t)(b * NH + h)) * SS + s) * HD + 2 * p] = __floats2half2_rn(x0, x1);
}

__global__ void rope_k_kernel(const float* __restrict__ kf,
                              const float* __restrict__ fc,
                              const float* __restrict__ fs,
                              __half* __restrict__ ko) {
    int idx = blockIdx.x * blockDim.x + threadIdx.x;
    int p   = idx & 63;
    int h   = (idx >> 6) & (NKV - 1);
    int row = idx >> 9;
    int s   = row & (SS - 1);
    int b   = row >> 11;
    float2 tv = *(const float2*)&kf[(size_t)row * KVDIM + h * HD + 2 * p];
    float c = fc[s * 64 + p], sn = fs[s * 64 + p];
    float x0 = tv.x * c - tv.y * sn;
    float x1 = tv.x * sn + tv.y * c;
    *(__half2*)&ko[(((size_t)(b * NKV + h)) * SS + s) * HD + 2 * p] = __floats2half2_rn(x0, x1);
}

__global__ void v_tr_kernel(const float* __restrict__ vf, __half* __restrict__ vo) {
    int idx = blockIdx.x * blockDim.x + threadIdx.x;   // MR*KVDIM/4
    int d4  = idx & 31;
    int h   = (idx >> 5) & (NKV - 1);
    int row = idx >> 8;
    int s   = row & (SS - 1);
    int b   = row >> 11;
    float4 v = ((const float4*)vf)[idx];
    uint2 o;
    o.x = packh2(v.x, v.y);
    o.y = packh2(v.z, v.w);
    *(uint2*)&vo[((((size_t)(b * NKV + h)) * SS + s) * HD) + d4 * 4] = o;
}

// ============================================================
// fp16 HMMA flash attention.
// Q tile 128 (8 warps x 16 rows), KV tile 64, double-buffered K/V.
// fp32 accumulators + online softmax. Output fp16 [row][h*128+d].
// ============================================================
#define QT 128
#define KT 64
#define LDK 136                 // halves per smem row (128 + 8 pad)
#define STGH (2 * KT * LDK)     // halves per stage (K + V)

__global__ __launch_bounds__(256, 1)
void attn_h16(const __half* __restrict__ Q, const __half* __restrict__ K,
              const __half* __restrict__ V, __half* __restrict__ O) {
    extern __shared__ __half sm[];
    const int t = threadIdx.x, lane = t & 31, w = t >> 5;
    const int l4 = lane & 3, g = lane >> 2, lr = lane & 15, lc = lane >> 4;
    const int qt = blockIdx.x, h = blockIdx.y, b = blockIdx.z;
    const int kvh = h >> 2, q0 = qt * QT;
    const __half* qg = Q + ((size_t)(b * NH + h) * SS + q0) * HD;
    const __half* kg = K + ((size_t)(b * NKV + kvh) * SS) * HD;
    const __half* vg = V + ((size_t)(b * NKV + kvh) * SS) * HD;
    const uint32_t smb = smem_u32(sm);
    const uint32_t qsm = smb + 2 * STGH * 2;

    // load Q tile (128 rows x 16 chunks of 16B)
    for (int i = t; i < 2048; i += 256) {
        int r = i >> 4, c = i & 15;
        cpa16(qsm + (r * LDK + c * 8) * 2, qg + (size_t)r * HD + c * 8);
    }
    CP_COMMIT;

#define LOADKV(tile, buf) do {                                                  \
    uint32_t _k = smb + (buf) * STGH * 2;                                       \
    uint32_t _v = _k + KT * LDK * 2;                                            \
    const __half* _gk = kg + (size_t)(tile) * KT * HD;                          \
    const __half* _gv = vg + (size_t)(tile) * KT * HD;                          \
    _Pragma("unroll")                                                           \
    for (int _i = 0; _i < 4; _i++) {                                            \
        int _id = _i * 256 + t; int _r = _id >> 4, _c = _id & 15;               \
        cpa16(_k + (_r * LDK + _c * 8) * 2, _gk + (size_t)_r * HD + _c * 8);    \
        cpa16(_v + (_r * LDK + _c * 8) * 2, _gv + (size_t)_r * HD + _c * 8);    \
    }                                                                           \
    CP_COMMIT; } while (0)

    const int ntiles = q0 / KT + 2;
    LOADKV(0, 0);

    CP_WAIT1;            // Q arrived (pending: KV0)
    __syncthreads();

    // Q fragments -> registers (8 k16 steps)
    uint32_t qf_[8][4];
    #pragma unroll
    for (int ks = 0; ks < 8; ks++)
        ldsm4(qf_[ks], qsm + ((w * 16 + lr) * LDK + ks * 16 + lc * 8) * 2);

    if (ntiles > 1) LOADKV(1, 1);

    float mx0 = -INFINITY, mx1 = -INFINITY, l0 = 0.f, l1 = 0.f;
    float oacc[16][4];
    #pragma unroll
    for (int j = 0; j < 16; j++)
        #pragma unroll
        for (int e = 0; e < 4; e++) oacc[j][e] = 0.f;

    for (int it = 0; it < ntiles; it++) {
        if (it + 1 < ntiles) { CP_WAIT1; } else { CP_WAIT0; }
        __syncthreads();
        const uint32_t bK = smb + (it & 1) * STGH * 2;
        const uint32_t bV = bK + KT * LDK * 2;
        const int kv0 = it * KT;

        // ---- scores = Q K^T (pre-scaled) ----
        float sc[8][4];
        #pragma unroll
        for (int f = 0; f < 8; f++)
            #pragma unroll
            for (int e = 0; e < 4; e++) sc[f][e] = 0.f;

        #pragma unroll
        for (int ks = 0; ks < 8; ks++) {
            #pragma unroll
            for (int np = 0; np < 4; np++) {
                uint32_t kb4[4];
                ldsm4(kb4, bK + ((np * 16 + lr) * LDK + ks * 16 + lc * 8) * 2);
                mma16816(sc[2 * np],     qf_[ks], kb4[0], kb4[2]);
                mma16816(sc[2 * np + 1], qf_[ks], kb4[1], kb4[3]);
            }
        }

        // ---- causal mask ----
        const int row0 = q0 + w * 16 + g;
        if (kv0 + KT - 1 > q0 + w * 16) {
            #pragma unroll
            for (int f = 0; f < 8; f++) {
                int c = kv0 + 8 * f + l4 * 2;
                if (c     > row0)     sc[f][0] = -1e30f;
                if (c + 1 > row0)     sc[f][1] = -1e30f;
                if (c     > row0 + 8) sc[f][2] = -1e30f;
                if (c + 1 > row0 + 8) sc[f][3] = -1e30f;
            }
        }

        // ---- online softmax ----
        float m0 = -INFINITY, m1 = -INFINITY;
        #pragma unroll
        for (int f = 0; f < 8; f++) {
            m0 = fmaxf(m0, fmaxf(sc[f][0], sc[f][1]));
            m1 = fmaxf(m1, fmaxf(sc[f][2], sc[f][3]));
        }
        m0 = fmaxf(m0, __shfl_xor_sync(0xffffffffu, m0, 1));
        m0 = fmaxf(m0, __shfl_xor_sync(0xffffffffu, m0, 2));
        m1 = fmaxf(m1, __shfl_xor_sync(0xffffffffu, m1, 1));
        m1 = fmaxf(m1, __shfl_xor_sync(0xffffffffu, m1, 2));
        float nm0 = fmaxf(mx0, m0), nm1 = fmaxf(mx1, m1);
        float cs0 = __expf(mx0 - nm0), cs1 = __expf(mx1 - nm1);
        mx0 = nm0; mx1 = nm1;

        float ps0 = 0.f, ps1 = 0.f;
        #pragma unroll
        for (int f = 0; f < 8; f++) {
            sc[f][0] = __expf(sc[f][0] - nm0);
            sc[f][1] = __expf(sc[f][1] - nm0);
            sc[f][2] = __expf(sc[f][2] - nm1);
            sc[f][3] = __expf(sc[f][3] - nm1);
            ps0 += sc[f][0] + sc[f][1];
            ps1 += sc[f][2] + sc[f][3];
        }
        l0 = l0 * cs0 + ps0;
        l1 = l1 * cs1 + ps1;
        #pragma unroll
        for (int j = 0; j < 16; j++) {
            oacc[j][0] *= cs0; oacc[j][1] *= cs0;
            oacc[j][2] *= cs1; oacc[j][3] *= cs1;
        }

        // ---- P fragments (fp16) ----
        uint32_t pf[4][4];
        #pragma unroll
        for (int kb = 0; kb < 4; kb++) {
            pf[kb][0] = packh2(sc[2 * kb][0],     sc[2 * kb][1]);
            pf[kb][1] = packh2(sc[2 * kb][2],     sc[2 * kb][3]);
            pf[kb][2] = packh2(sc[2 * kb + 1][0], sc[2 * kb + 1][1]);
            pf[kb][3] = packh2(sc[2 * kb + 1][2], sc[2 * kb + 1][3]);
        }

        // ---- out += P V  (V via ldmatrix.trans: {r0,r1}=n-group d, {r2,r3}=d+8) ----
        #pragma unroll
        for (int kb = 0; kb < 4; kb++) {
            #pragma unroll
            for (int dj = 0; dj < 8; dj++) {
                uint32_t vb[4];
                ldsm4t(vb, bV + ((kb * 16 + lr) * LDK + dj * 16 + lc * 8) * 2);
                mma16816(oacc[2 * dj],     pf[kb], vb[0], vb[1]);
                mma16816(oacc[2 * dj + 1], pf[kb], vb[2], vb[3]);
            }
        }

        __syncthreads();
        if (it + 2 < ntiles) LOADKV(it + 2, it & 1);
    }

    // ---- finalize ----
    l0 += __shfl_xor_sync(0xffffffffu, l0, 1);
    l0 += __shfl_xor_sync(0xffffffffu, l0, 2);
    l1 += __shfl_xor_sync(0xffffffffu, l1, 1);
    l1 += __shfl_xor_sync(0xffffffffu, l1, 2);
    float inv0 = 1.f / l0, inv1 = 1.f / l1;

    const int row0 = q0 + w * 16 + g;
    __half* o0 = O + ((size_t)(b * SS) + row0) * DIM + h * HD;
    __half* o1 = o0 + (size_t)8 * DIM;
    #pragma unroll
    for (int j = 0; j < 16; j++) {
        int col = 8 * j + l4 * 2;
        *(__half2*)&o0[col] = __floats2half2_rn(oacc[j][0] * inv0, oacc[j][1] * inv0);
        *(__half2*)&o1[col] = __floats2half2_rn(oacc[j][2] * inv1, oacc[j][3] * inv1);
    }
}

// ============================================================
extern "C" void kernel_launch(void* const* d_in, const int* in_sizes, int n_in,
                              void* d_out, int out_size) {
    const float* x  = (const float*)d_in[0];
    const float* wq = (const float*)d_in[1];
    const float* wk = (const float*)d_in[2];
    const float* wv = (const float*)d_in[3];
    const float* wo = (const float*)d_in[4];
    const float* fc = (const float*)d_in[5];
    const float* fs = (const float*)d_in[6];
    float* out = (float*)d_out;

    float *qf, *kf, *vf;
    __half *qh, *kh, *vh, *ath, *xh, *wqh, *wkh, *wvh, *woh;
    cudaGetSymbolAddress((void**)&qf,  g_qf);
    cudaGetSymbolAddress((void**)&kf,  g_kf);
    cudaGetSymbolAddress((void**)&vf,  g_vf);
    cudaGetSymbolAddress((void**)&qh,  g_qh);
    cudaGetSymbolAddress((void**)&kh,  g_kh);
    cudaGetSymbolAddress((void**)&vh,  g_vh);
    cudaGetSymbolAddress((void**)&ath, g_ath);
    cudaGetSymbolAddress((void**)&xh,  g_xh);
    cudaGetSymbolAddress((void**)&wqh, g_wqh);
    cudaGetSymbolAddress((void**)&wkh, g_wkh);
    cudaGetSymbolAddress((void**)&wvh, g_wvh);
    cudaGetSymbolAddress((void**)&woh, g_woh);

    const int ATTN_SMEM = (2 * STGH + QT * LDK) * 2;   // 104448 bytes
    cudaFuncSetAttribute(attn_h16, cudaFuncAttributeMaxDynamicSharedMemorySize, ATTN_SMEM);

    // fp16 copies
    cvt_h<<<(MR * DIM / 2 + 255) / 256, 256>>>(x,  xh,  MR * DIM / 2);
    cvt_h<<<((size_t)DIM * DIM / 2 + 255) / 256, 256>>>(wq, wqh, DIM * DIM / 2);
    cvt_h<<<((size_t)KVDIM * DIM / 2 + 255) / 256, 256>>>(wk, wkh, KVDIM * DIM / 2);
    cvt_h<<<((size_t)KVDIM * DIM / 2 + 255) / 256, 256>>>(wv, wvh, KVDIM * DIM / 2);
    cvt_h<<<((size_t)DIM * DIM / 2 + 255) / 256, 256>>>(wo, woh, DIM * DIM / 2);

    // QKV projections (fp16 HMMA)
    gemm_nt_h16<<<dim3(DIM / 128,   MR / 128), 256>>>(xh, wqh, qf, MR, DIM,   DIM);
    gemm_nt_h16<<<dim3(KVDIM / 128, MR / 128), 256>>>(xh, wkh, kf, MR, KVDIM, DIM);
    gemm_nt_h16<<<dim3(KVDIM / 128, MR / 128), 256>>>(xh, wvh, vf, MR, KVDIM, DIM);

    // RoPE + layout transforms (fp16 out)
    rope_q_kernel<<<(MR * NH  * 64) / 256, 256>>>(qf, fc, fs, qh);
    rope_k_kernel<<<(MR * NKV * 64) / 256, 256>>>(kf, fc, fs, kh);
    v_tr_kernel  <<<(MR * KVDIM / 4) / 256, 256>>>(vf, vh);

    // causal GQA attention (fp16 HMMA, fp32 softmax)
    attn_h16<<<dim3(SS / QT, NH, BB), 256, ATTN_SMEM>>>(qh, kh, vh, ath);

    // output projection (fp16 HMMA)
    gemm_nt_h16<<<dim3(DIM / 128, MR / 128), 256>>>(ath, woh, out, MR, DIM, DIM);
}